// round 11
// baseline (speedup 1.0000x reference)
#include <cuda_runtime.h>
#include <cuda_fp16.h>
#include <cstdint>

#define TPB     512
#define TILE_M  32
#define STATE   24
#define L1D     100
#define L2D     100
#define NHEAD   27
#define ACT     6

#define NT12    13
#define NT3     4
#define KS1     2
#define KS23    7

#define S1_32   36
#define LO1     16
#define S2_32   116
#define LO2     56

// ---- smem layout (b32 word offsets) ----
#define F_BP1   0
#define F_BP2   (F_BP1 + KS1*NT12*32*4)         //  3328
#define F_BP3   (F_BP2 + KS23*NT12*32*4)        // 14976
#define F_PIPE  (F_BP3 + KS23*NT3*32*4)         // 18560
#define P_AS1   0
#define P_AS2   (TILE_M*S1_32)                  // 1152
#define P_CHOL  (P_AS2 + TILE_M*S2_32)          // 4864
#define P_MEAN  (P_CHOL + TILE_M*36)            // 6016
#define PIPE_W  (P_MEAN + TILE_M*ACT)           // 6208 words
#define F_TOTAL (F_PIPE + 4*PIPE_W)             // 43392 words = 173568 B

__constant__ int c_pos[21]   = {0,6,7,12,13,14,18,19,20,21,24,25,26,27,28,30,31,32,33,34,35};
__constant__ int c_upper[15] = {1,2,3,4,5,8,9,10,11,15,16,17,22,23,29};

__device__ __forceinline__ uint32_t packh(__half a, __half b) {
    return (uint32_t)__half_as_ushort(a) | ((uint32_t)__half_as_ushort(b) << 16);
}
__device__ __forceinline__ void split2(float v0, float v1, uint32_t& hi, uint32_t& lo) {
    __half h0 = __float2half_rn(v0), h1 = __float2half_rn(v1);
    __half l0 = __float2half_rn(v0 - __half2float(h0));
    __half l1 = __float2half_rn(v1 - __half2float(h1));
    hi = packh(h0, h1); lo = packh(l0, l1);
}

__device__ __forceinline__ void mma16(float* c, const uint32_t* a, uint32_t b0, uint32_t b1) {
    asm volatile("mma.sync.aligned.m16n8k16.row.col.f32.f16.f16.f32 "
                 "{%0,%1,%2,%3},{%4,%5,%6,%7},{%8,%9},{%0,%1,%2,%3};"
                 : "+f"(c[0]), "+f"(c[1]), "+f"(c[2]), "+f"(c[3])
                 : "r"(a[0]), "r"(a[1]), "r"(a[2]), "r"(a[3]), "r"(b0), "r"(b1));
}

__device__ __forceinline__ void ldsm_x4(uint32_t (&r)[4], uint32_t saddr) {
    asm volatile("ldmatrix.sync.aligned.m8n8.x4.shared.b16 {%0,%1,%2,%3}, [%4];"
                 : "=r"(r[0]), "=r"(r[1]), "=r"(r[2]), "=r"(r[3]) : "r"(saddr));
}

#define PIPE_BAR() asm volatile("bar.sync %0, 128;" :: "r"(1 + pipe) : "memory")

extern __shared__ uint32_t smem[];

// 3-term f16 warp GEMM; A fragments via ldmatrix.x4 (hi and lo planes).
template<int KS, int MT, int NTW>
__device__ __forceinline__ void wgemm_ldsm(const uint32_t* __restrict__ A32, int S32v, int LO,
                                           const uint4* __restrict__ Bp,
                                           int NTT, int nt0, int cnt,
                                           int wrow, int lane,
                                           float (&c)[MT][NTW][4])
{
    #pragma unroll
    for (int mt = 0; mt < MT; mt++)
        #pragma unroll
        for (int j = 0; j < NTW; j++)
            #pragma unroll
            for (int i = 0; i < 4; i++) c[mt][j][i] = 0.0f;

    // per-lane LDSM base: row = wrow + (lane&15), +16B column step for lanes>=16
    const uint32_t abase = (uint32_t)__cvta_generic_to_shared(A32)
                         + ((uint32_t)((wrow + (lane & 15)) * S32v + (lane >> 4) * 4)) * 4u;

    #pragma unroll 1
    for (int ks = 0; ks < KS; ks++) {
        uint4 bfr[NTW];
        #pragma unroll
        for (int j = 0; j < NTW; j++)
            if (j < cnt) bfr[j] = Bp[(ks * NTT + nt0 + j) * 32 + lane];

        uint32_t ah[MT][4], al[MT][4];
        #pragma unroll
        for (int mt = 0; mt < MT; mt++) {
            const uint32_t ad = abase + (uint32_t)(mt * 16 * S32v * 4 + ks * 32);
            ldsm_x4(ah[mt], ad);
            ldsm_x4(al[mt], ad + (uint32_t)(LO * 4));
        }

        #pragma unroll
        for (int term = 0; term < 3; term++)
            #pragma unroll
            for (int j = 0; j < NTW; j++) {
                if (j >= cnt) continue;
                uint32_t b0 = (term == 2) ? bfr[j].z : bfr[j].x;
                uint32_t b1 = (term == 2) ? bfr[j].w : bfr[j].y;
                #pragma unroll
                for (int mt = 0; mt < MT; mt++)
                    mma16(c[mt][j], (term == 1) ? al[mt] : ah[mt], b0, b1);
            }
    }
}

template<int MT, int NTW>
__device__ __forceinline__ void epi_relu16(float (&c)[MT][NTW][4], uint32_t* A2,
                                           int wrow, int nt0, int cnt, int g, int t)
{
    #pragma unroll
    for (int mt = 0; mt < MT; mt++) {
        const int row = wrow + 16 * mt + g;
        #pragma unroll
        for (int j = 0; j < NTW; j++) {
            if (j >= cnt) continue;
            const int nt = nt0 + j;
            if (nt == 12 && t >= 2) continue;      // cols >= 100
            const int pi = 4 * nt + t;
            uint32_t h, l;
            split2(fmaxf(c[mt][j][0], 0.f), fmaxf(c[mt][j][1], 0.f), h, l);
            A2[row * S2_32 + pi] = h;  A2[row * S2_32 + LO2 + pi] = l;
            split2(fmaxf(c[mt][j][2], 0.f), fmaxf(c[mt][j][3], 0.f), h, l);
            A2[(row + 8) * S2_32 + pi] = h;  A2[(row + 8) * S2_32 + LO2 + pi] = l;
        }
    }
}

__global__ void __launch_bounds__(TPB, 1)
actor_mma(const float* __restrict__ states,
          const float* __restrict__ W1, const float* __restrict__ b1,
          const float* __restrict__ W2, const float* __restrict__ b2,
          const float* __restrict__ Wm, const float* __restrict__ bm,
          const float* __restrict__ Wc, const float* __restrict__ bc,
          float* __restrict__ out, int B)
{
    const int tid  = threadIdx.x;
    const int lane = tid & 31;
    const int wid  = tid >> 5;
    const int g    = lane >> 2;
    const int t    = lane & 3;

    const int pipe = wid >> 2;        // 0..3 — one warp per SMSP per pipeline
    const int w    = wid & 3;
    const int ptid = tid & 127;

    // layers 1,2 (M=32): M2(full) x N4 — B fragments read once per tile
    const int nt0  = (w == 0) ? 0 : (1 + 3 * w);   // {0,4,7,10}
    const int ncnt = (w == 0) ? 4 : 3;
    // head (M=32, N=32): M2 x N2
    const int wrow3 = (w & 1) * 16;
    const int nt03  = (w >> 1) * 2;

    uint32_t* pb   = smem + F_PIPE + pipe * PIPE_W;
    uint32_t* As1  = pb + P_AS1;
    uint32_t* As2  = pb + P_AS2;
    float* sChol   = reinterpret_cast<float*>(pb + P_CHOL);
    float* sMean   = reinterpret_cast<float*>(pb + P_MEAN);
    const uint4* Bp1 = reinterpret_cast<const uint4*>(smem + F_BP1);
    const uint4* Bp2 = reinterpret_cast<const uint4*>(smem + F_BP2);
    const uint4* Bp3 = reinterpret_cast<const uint4*>(smem + F_BP3);

    // ---- stage packed f16 hi/lo weight fragments (biases folded as K-column) ----
    for (int i = tid; i < KS1 * NT12 * 32; i += TPB) {
        int ln = i & 31, slot = i >> 5, ks = slot / NT12, nt = slot - ks * NT12;
        int n = (ln >> 2) + 8 * nt, k0 = 16 * ks + 2 * (ln & 3);
        float wv[4];
        #pragma unroll
        for (int q = 0; q < 4; q++) {
            int k = k0 + (q >> 1) * 8 + (q & 1);
            wv[q] = (n < L1D) ? (k < STATE ? W1[n * STATE + k] : (k == STATE ? b1[n] : 0.f)) : 0.f;
        }
        uint4 fr; uint32_t lo0, lo1;
        split2(wv[0], wv[1], fr.x, lo0); split2(wv[2], wv[3], fr.y, lo1);
        fr.z = lo0; fr.w = lo1;
        reinterpret_cast<uint4*>(smem + F_BP1)[i] = fr;
    }
    for (int i = tid; i < KS23 * NT12 * 32; i += TPB) {
        int ln = i & 31, slot = i >> 5, ks = slot / NT12, nt = slot - ks * NT12;
        int n = (ln >> 2) + 8 * nt, k0 = 16 * ks + 2 * (ln & 3);
        float wv[4];
        #pragma unroll
        for (int q = 0; q < 4; q++) {
            int k = k0 + (q >> 1) * 8 + (q & 1);
            wv[q] = (n < L2D) ? (k < L1D ? W2[n * L1D + k] : (k == L1D ? b2[n] : 0.f)) : 0.f;
        }
        uint4 fr; uint32_t lo0, lo1;
        split2(wv[0], wv[1], fr.x, lo0); split2(wv[2], wv[3], fr.y, lo1);
        fr.z = lo0; fr.w = lo1;
        reinterpret_cast<uint4*>(smem + F_BP2)[i] = fr;
    }
    for (int i = tid; i < KS23 * NT3 * 32; i += TPB) {
        int ln = i & 31, slot = i >> 5, ks = slot / NT3, nt = slot - ks * NT3;
        int n = (ln >> 2) + 8 * nt, k0 = 16 * ks + 2 * (ln & 3);
        float wv[4];
        #pragma unroll
        for (int q = 0; q < 4; q++) {
            int k = k0 + (q >> 1) * 8 + (q & 1);
            float v = 0.f;
            if (n < ACT)        v = k < L2D ? Wm[n * L2D + k] : (k == L2D ? bm[n] : 0.f);
            else if (n < NHEAD) v = k < L2D ? Wc[(n - ACT) * L2D + k] : (k == L2D ? bc[n - ACT] : 0.f);
            wv[q] = v;
        }
        uint4 fr; uint32_t lo0, lo1;
        split2(wv[0], wv[1], fr.x, lo0); split2(wv[2], wv[3], fr.y, lo1);
        fr.z = lo0; fr.w = lo1;
        reinterpret_cast<uint4*>(smem + F_BP3)[i] = fr;
    }
    // one-time per-pipeline activation pad init
    for (int i = ptid; i < TILE_M * S2_32; i += 128) As2[i] = 0u;
    __syncthreads();
    if (ptid < TILE_M) {
        const uint32_t one = packh(__float2half_rn(1.f), __ushort_as_half(0));
        As2[ptid * S2_32 + 50] = one;                 // bias col 100
        uint32_t* rr = As1 + ptid * S1_32;
        rr[12] = one;  rr[LO1 + 12] = 0u;             // bias col 24
        #pragma unroll
        for (int p = 13; p < 16; p++) { rr[p] = 0u; rr[LO1 + p] = 0u; }
    }
    __syncthreads();

    const int ntiles = (B + TILE_M - 1) / TILE_M;
    const int stride = gridDim.x * 4;
    const int tile0  = blockIdx.x * 4 + pipe;

    // ---- prefetch first tile's X (2 threads per row, 3 float4 each) ----
    float4 px0, px1, px2;
    if (ptid < 2 * TILE_M && tile0 < ntiles) {
        long m = (long)tile0 * TILE_M + (ptid >> 1); if (m >= B) m = B - 1;
        const float4* src = reinterpret_cast<const float4*>(states + m * STATE) + (ptid & 1) * 3;
        px0 = src[0]; px1 = src[1]; px2 = src[2];
    }

    for (int tile = tile0; tile < ntiles; tile += stride) {
        if (ptid < 2 * TILE_M) {
            const int row = ptid >> 1, half = ptid & 1;
            uint32_t* rh = As1 + row * S1_32 + half * 6;
            uint32_t h, l;
            split2(px0.x, px0.y, h, l); rh[0] = h; rh[LO1 + 0] = l;
            split2(px0.z, px0.w, h, l); rh[1] = h; rh[LO1 + 1] = l;
            split2(px1.x, px1.y, h, l); rh[2] = h; rh[LO1 + 2] = l;
            split2(px1.z, px1.w, h, l); rh[3] = h; rh[LO1 + 3] = l;
            split2(px2.x, px2.y, h, l); rh[4] = h; rh[LO1 + 4] = l;
            split2(px2.z, px2.w, h, l); rh[5] = h; rh[LO1 + 5] = l;
        }
        {
            int nxt = tile + stride;
            if (ptid < 2 * TILE_M && nxt < ntiles) {
                long m = (long)nxt * TILE_M + (ptid >> 1); if (m >= B) m = B - 1;
                const float4* src = reinterpret_cast<const float4*>(states + m * STATE) + (ptid & 1) * 3;
                px0 = src[0]; px1 = src[1]; px2 = src[2];
            }
        }
        PIPE_BAR();                                        // S1: X ready

        // ---- layer 1: As1 -> As2 (full-M per warp, unique N) ----
        {
            float c1[2][4][4];
            wgemm_ldsm<KS1, 2, 4>(As1, S1_32, LO1, Bp1, NT12, nt0, ncnt, 0, lane, c1);
            epi_relu16<2, 4>(c1, As2, 0, nt0, ncnt, g, t);
        }
        PIPE_BAR();                                        // S2: hidden1 ready

        // ---- layer 2: As2 -> As2 ----
        {
            float c2[2][4][4];
            wgemm_ldsm<KS23, 2, 4>(As2, S2_32, LO2, Bp2, NT12, nt0, ncnt, 0, lane, c2);
            PIPE_BAR();                                    // S3: reads done
            epi_relu16<2, 4>(c2, As2, 0, nt0, ncnt, g, t);
        }
        PIPE_BAR();                                        // S4: hidden2 ready

        // ---- head gemm + staged activation scatter ----
        {
            float c3[1][2][4];
            wgemm_ldsm<KS23, 1, 2>(As2, S2_32, LO2, Bp3, NT3, nt03, 2, wrow3, lane, c3);
            #pragma unroll
            for (int j = 0; j < 2; j++)
                #pragma unroll
                for (int i = 0; i < 4; i++) {
                    int row = wrow3 + g + ((i >= 2) ? 8 : 0);
                    int col = 8 * (nt03 + j) + 2 * t + (i & 1);
                    float v = c3[0][j][i];
                    if (col < ACT) {
                        sMean[row * ACT + col] = tanhf(v);
                    } else if (col < NHEAD) {
                        float sp = fmaxf(v, 0.f) + log1pf(expf(-fabsf(v)));
                        sChol[row * 36 + c_pos[col - ACT]] = sp;
                    }
                }
            if (ptid < TILE_M) {
                #pragma unroll
                for (int j = 0; j < 15; j++) sChol[ptid * 36 + c_upper[j]] = 0.0f;
            }
        }
        PIPE_BAR();                                        // S5: staged

        // ---- coalesced writeback ----
        if ((tile + 1) * TILE_M <= B) {
            float4* pm = reinterpret_cast<float4*>(out + (size_t)tile * (TILE_M * ACT));
            const float4* sm4 = reinterpret_cast<const float4*>(sMean);
            for (int i = ptid; i < TILE_M * ACT / 4; i += 128) pm[i] = sm4[i];
            float4* pc = reinterpret_cast<float4*>(out + (size_t)B * ACT + (size_t)tile * (TILE_M * 36));
            const float4* sc4 = reinterpret_cast<const float4*>(sChol);
            for (int i = ptid; i < TILE_M * 36 / 4; i += 128) pc[i] = sc4[i];
        } else {
            int nrow = B - tile * TILE_M;
            for (int i = ptid; i < nrow * ACT; i += 128)
                out[(size_t)tile * (TILE_M * ACT) + i] = sMean[i];
            for (int i = ptid; i < nrow * 36; i += 128)
                out[(size_t)B * ACT + (size_t)tile * (TILE_M * 36) + i] = sChol[i];
        }
        PIPE_BAR();                                        // S6: stage free
    }
}

extern "C" void kernel_launch(void* const* d_in, const int* in_sizes, int n_in,
                              void* d_out, int out_size)
{
    const float* states = (const float*)d_in[0];
    const float* W1 = (const float*)d_in[1];
    const float* b1 = (const float*)d_in[2];
    const float* W2 = (const float*)d_in[3];
    const float* b2 = (const float*)d_in[4];
    const float* Wm = (const float*)d_in[5];
    const float* bm = (const float*)d_in[6];
    const float* Wc = (const float*)d_in[7];
    const float* bc = (const float*)d_in[8];
    float* out = (float*)d_out;

    const int B = in_sizes[0] / STATE;
    const int ntiles = (B + TILE_M - 1) / TILE_M;
    const size_t smem_bytes = (size_t)F_TOTAL * 4;   // 173568 B

    cudaFuncSetAttribute(actor_mma,
                         cudaFuncAttributeMaxDynamicSharedMemorySize,
                         (int)smem_bytes);

    int nstreams = (ntiles + 3) / 4;
    int grid = nstreams < 152 ? nstreams : 152;      // 1 CTA/SM, 4 pipelines each
    actor_mma<<<grid, TPB, smem_bytes>>>(states, W1, b1, W2, b2,
                                         Wm, bm, Wc, bc, out, B);
}

// round 12
// speedup vs baseline: 1.0753x; 1.0753x over previous
#include <cuda_runtime.h>
#include <cuda_fp16.h>
#include <cstdint>

#define TPB     512
#define TILE_M  32
#define STATE   24
#define L1D     100
#define L2D     100
#define NHEAD   27
#define ACT     6

#define NT12    13
#define NT3     4
#define KS1     2
#define KS23    7

#define S1_32   36
#define LO1     16
#define S2_32   116
#define LO2     56

// ---- smem layout (b32 word offsets) ----
#define F_BP1   0
#define F_BP2   (F_BP1 + KS1*NT12*32*4)         //  3328
#define F_BP3   (F_BP2 + KS23*NT12*32*4)        // 14976
#define F_PIPE  (F_BP3 + KS23*NT3*32*4)         // 18560
#define P_AS1   0
#define P_AS2   (TILE_M*S1_32)                  // 1152
#define P_CHOL  (P_AS2 + TILE_M*S2_32)          // 4864
#define P_MEAN  (P_CHOL + TILE_M*36)            // 6016
#define PIPE_W  (P_MEAN + TILE_M*ACT)           // 6208 words
#define F_TOTAL (F_PIPE + 4*PIPE_W)             // 43392 words = 173568 B

__constant__ int c_pos[21]   = {0,6,7,12,13,14,18,19,20,21,24,25,26,27,28,30,31,32,33,34,35};
__constant__ int c_upper[15] = {1,2,3,4,5,8,9,10,11,15,16,17,22,23,29};

__device__ __forceinline__ uint32_t packh(__half a, __half b) {
    return (uint32_t)__half_as_ushort(a) | ((uint32_t)__half_as_ushort(b) << 16);
}
__device__ __forceinline__ void split2(float v0, float v1, uint32_t& hi, uint32_t& lo) {
    __half h0 = __float2half_rn(v0), h1 = __float2half_rn(v1);
    __half l0 = __float2half_rn(v0 - __half2float(h0));
    __half l1 = __float2half_rn(v1 - __half2float(h1));
    hi = packh(h0, h1); lo = packh(l0, l1);
}

__device__ __forceinline__ void mma16(float* c, const uint32_t* a, uint32_t b0, uint32_t b1) {
    asm volatile("mma.sync.aligned.m16n8k16.row.col.f32.f16.f16.f32 "
                 "{%0,%1,%2,%3},{%4,%5,%6,%7},{%8,%9},{%0,%1,%2,%3};"
                 : "+f"(c[0]), "+f"(c[1]), "+f"(c[2]), "+f"(c[3])
                 : "r"(a[0]), "r"(a[1]), "r"(a[2]), "r"(a[3]), "r"(b0), "r"(b1));
}

__device__ __forceinline__ void ldsm_x4(uint32_t (&r)[4], uint32_t saddr) {
    asm volatile("ldmatrix.sync.aligned.m8n8.x4.shared.b16 {%0,%1,%2,%3}, [%4];"
                 : "=r"(r[0]), "=r"(r[1]), "=r"(r[2]), "=r"(r[3]) : "r"(saddr));
}

#define PIPE_BAR() asm volatile("bar.sync %0, 128;" :: "r"(1 + pipe) : "memory")

extern __shared__ uint32_t smem[];

// 3-term f16 warp GEMM; 16 rows per warp (MT=1), A fragments via ldmatrix.x4.
template<int KS, int NTW>
__device__ __forceinline__ void wgemm_ldsm(const uint32_t* __restrict__ A32, int S32v, int LO,
                                           const uint4* __restrict__ Bp,
                                           int NTT, int nt0, int cnt,
                                           int wrow, int lane,
                                           float (&c)[NTW][4])
{
    #pragma unroll
    for (int j = 0; j < NTW; j++)
        #pragma unroll
        for (int i = 0; i < 4; i++) c[j][i] = 0.0f;

    // LDSM.x4 lane address: rows wrow+(lane&15), k-half select by lane>>4 (+16B)
    const uint32_t abase = (uint32_t)__cvta_generic_to_shared(A32)
                         + ((uint32_t)((wrow + (lane & 15)) * S32v + (lane >> 4) * 4)) * 4u;

    #pragma unroll 1
    for (int ks = 0; ks < KS; ks++) {
        uint4 bfr[NTW];
        #pragma unroll
        for (int j = 0; j < NTW; j++)
            if (j < cnt) bfr[j] = Bp[(ks * NTT + nt0 + j) * 32 + lane];

        uint32_t ah[4], al[4];
        {
            const uint32_t ad = abase + (uint32_t)(ks * 32);
            ldsm_x4(ah, ad);
            ldsm_x4(al, ad + (uint32_t)(LO * 4));
        }

        #pragma unroll
        for (int term = 0; term < 3; term++)
            #pragma unroll
            for (int j = 0; j < NTW; j++) {
                if (j >= cnt) continue;
                uint32_t b0 = (term == 2) ? bfr[j].z : bfr[j].x;
                uint32_t b1 = (term == 2) ? bfr[j].w : bfr[j].y;
                mma16(c[j], (term == 1) ? al : ah, b0, b1);
            }
    }
}

template<int NTW>
__device__ __forceinline__ void epi_relu16(float (&c)[NTW][4], uint32_t* A2,
                                           int wrow, int nt0, int cnt, int g, int t)
{
    const int row = wrow + g;
    #pragma unroll
    for (int j = 0; j < NTW; j++) {
        if (j >= cnt) continue;
        const int nt = nt0 + j;
        if (nt == 12 && t >= 2) continue;      // cols >= 100
        const int pi = 4 * nt + t;
        uint32_t h, l;
        split2(fmaxf(c[j][0], 0.f), fmaxf(c[j][1], 0.f), h, l);
        A2[row * S2_32 + pi] = h;  A2[row * S2_32 + LO2 + pi] = l;
        split2(fmaxf(c[j][2], 0.f), fmaxf(c[j][3], 0.f), h, l);
        A2[(row + 8) * S2_32 + pi] = h;  A2[(row + 8) * S2_32 + LO2 + pi] = l;
    }
}

__global__ void __launch_bounds__(TPB, 1)
actor_mma(const float* __restrict__ states,
          const float* __restrict__ W1, const float* __restrict__ b1,
          const float* __restrict__ W2, const float* __restrict__ b2,
          const float* __restrict__ Wm, const float* __restrict__ bm,
          const float* __restrict__ Wc, const float* __restrict__ bc,
          float* __restrict__ out, int B)
{
    const int tid  = threadIdx.x;
    const int lane = tid & 31;
    const int wid  = tid >> 5;
    const int g    = lane >> 2;
    const int t    = lane & 3;

    const int pipe = wid >> 2;        // 0..3 — one warp per SMSP per pipeline
    const int w    = wid & 3;
    const int ptid = tid & 127;

    // layers 1,2 (M=32): M2 x N2 -> warp: 16 rows, 7-or-6 n-tiles (balanced)
    const int wrow = (w & 1) * 16;
    const int nt0  = (w >> 1) * 7;                 // {0, 7}
    const int ncnt = (w >> 1) ? 6 : 7;
    // head (M=32, N=32): M2 x N2
    const int wrow3 = (w & 1) * 16;
    const int nt03  = (w >> 1) * 2;

    uint32_t* pb   = smem + F_PIPE + pipe * PIPE_W;
    uint32_t* As1  = pb + P_AS1;
    uint32_t* As2  = pb + P_AS2;
    float* sChol   = reinterpret_cast<float*>(pb + P_CHOL);
    float* sMean   = reinterpret_cast<float*>(pb + P_MEAN);
    const uint4* Bp1 = reinterpret_cast<const uint4*>(smem + F_BP1);
    const uint4* Bp2 = reinterpret_cast<const uint4*>(smem + F_BP2);
    const uint4* Bp3 = reinterpret_cast<const uint4*>(smem + F_BP3);

    // ---- stage packed f16 hi/lo weight fragments (biases folded as K-column) ----
    for (int i = tid; i < KS1 * NT12 * 32; i += TPB) {
        int ln = i & 31, slot = i >> 5, ks = slot / NT12, nt = slot - ks * NT12;
        int n = (ln >> 2) + 8 * nt, k0 = 16 * ks + 2 * (ln & 3);
        float wv[4];
        #pragma unroll
        for (int q = 0; q < 4; q++) {
            int k = k0 + (q >> 1) * 8 + (q & 1);
            wv[q] = (n < L1D) ? (k < STATE ? W1[n * STATE + k] : (k == STATE ? b1[n] : 0.f)) : 0.f;
        }
        uint4 fr; uint32_t lo0, lo1;
        split2(wv[0], wv[1], fr.x, lo0); split2(wv[2], wv[3], fr.y, lo1);
        fr.z = lo0; fr.w = lo1;
        reinterpret_cast<uint4*>(smem + F_BP1)[i] = fr;
    }
    for (int i = tid; i < KS23 * NT12 * 32; i += TPB) {
        int ln = i & 31, slot = i >> 5, ks = slot / NT12, nt = slot - ks * NT12;
        int n = (ln >> 2) + 8 * nt, k0 = 16 * ks + 2 * (ln & 3);
        float wv[4];
        #pragma unroll
        for (int q = 0; q < 4; q++) {
            int k = k0 + (q >> 1) * 8 + (q & 1);
            wv[q] = (n < L2D) ? (k < L1D ? W2[n * L1D + k] : (k == L1D ? b2[n] : 0.f)) : 0.f;
        }
        uint4 fr; uint32_t lo0, lo1;
        split2(wv[0], wv[1], fr.x, lo0); split2(wv[2], wv[3], fr.y, lo1);
        fr.z = lo0; fr.w = lo1;
        reinterpret_cast<uint4*>(smem + F_BP2)[i] = fr;
    }
    for (int i = tid; i < KS23 * NT3 * 32; i += TPB) {
        int ln = i & 31, slot = i >> 5, ks = slot / NT3, nt = slot - ks * NT3;
        int n = (ln >> 2) + 8 * nt, k0 = 16 * ks + 2 * (ln & 3);
        float wv[4];
        #pragma unroll
        for (int q = 0; q < 4; q++) {
            int k = k0 + (q >> 1) * 8 + (q & 1);
            float v = 0.f;
            if (n < ACT)        v = k < L2D ? Wm[n * L2D + k] : (k == L2D ? bm[n] : 0.f);
            else if (n < NHEAD) v = k < L2D ? Wc[(n - ACT) * L2D + k] : (k == L2D ? bc[n - ACT] : 0.f);
            wv[q] = v;
        }
        uint4 fr; uint32_t lo0, lo1;
        split2(wv[0], wv[1], fr.x, lo0); split2(wv[2], wv[3], fr.y, lo1);
        fr.z = lo0; fr.w = lo1;
        reinterpret_cast<uint4*>(smem + F_BP3)[i] = fr;
    }
    // one-time per-pipeline activation pad init
    for (int i = ptid; i < TILE_M * S2_32; i += 128) As2[i] = 0u;
    __syncthreads();
    if (ptid < TILE_M) {
        const uint32_t one = packh(__float2half_rn(1.f), __ushort_as_half(0));
        As2[ptid * S2_32 + 50] = one;                 // bias col 100
        uint32_t* rr = As1 + ptid * S1_32;
        rr[12] = one;  rr[LO1 + 12] = 0u;             // bias col 24
        #pragma unroll
        for (int p = 13; p < 16; p++) { rr[p] = 0u; rr[LO1 + p] = 0u; }
    }
    __syncthreads();

    const int ntiles = (B + TILE_M - 1) / TILE_M;
    const int stride = gridDim.x * 4;
    const int tile0  = blockIdx.x * 4 + pipe;

    // ---- prefetch first tile's X (2 threads per row, 3 float4 each) ----
    float4 px0, px1, px2;
    if (ptid < 2 * TILE_M && tile0 < ntiles) {
        long m = (long)tile0 * TILE_M + (ptid >> 1); if (m >= B) m = B - 1;
        const float4* src = reinterpret_cast<const float4*>(states + m * STATE) + (ptid & 1) * 3;
        px0 = src[0]; px1 = src[1]; px2 = src[2];
    }

    for (int tile = tile0; tile < ntiles; tile += stride) {
        if (ptid < 2 * TILE_M) {
            const int row = ptid >> 1, half = ptid & 1;
            uint32_t* rh = As1 + row * S1_32 + half * 6;
            uint32_t h, l;
            split2(px0.x, px0.y, h, l); rh[0] = h; rh[LO1 + 0] = l;
            split2(px0.z, px0.w, h, l); rh[1] = h; rh[LO1 + 1] = l;
            split2(px1.x, px1.y, h, l); rh[2] = h; rh[LO1 + 2] = l;
            split2(px1.z, px1.w, h, l); rh[3] = h; rh[LO1 + 3] = l;
            split2(px2.x, px2.y, h, l); rh[4] = h; rh[LO1 + 4] = l;
            split2(px2.z, px2.w, h, l); rh[5] = h; rh[LO1 + 5] = l;
        }
        {
            int nxt = tile + stride;
            if (ptid < 2 * TILE_M && nxt < ntiles) {
                long m = (long)nxt * TILE_M + (ptid >> 1); if (m >= B) m = B - 1;
                const float4* src = reinterpret_cast<const float4*>(states + m * STATE) + (ptid & 1) * 3;
                px0 = src[0]; px1 = src[1]; px2 = src[2];
            }
        }
        PIPE_BAR();                                        // S1: X ready

        // ---- layer 1: As1 -> As2 ----
        {
            float c1[7][4];
            wgemm_ldsm<KS1, 7>(As1, S1_32, LO1, Bp1, NT12, nt0, ncnt, wrow, lane, c1);
            epi_relu16<7>(c1, As2, wrow, nt0, ncnt, g, t);
        }
        PIPE_BAR();                                        // S2: hidden1 ready

        // ---- layer 2: As2 -> As2 ----
        {
            float c2[7][4];
            wgemm_ldsm<KS23, 7>(As2, S2_32, LO2, Bp2, NT12, nt0, ncnt, wrow, lane, c2);
            PIPE_BAR();                                    // S3: reads done
            epi_relu16<7>(c2, As2, wrow, nt0, ncnt, g, t);
        }
        PIPE_BAR();                                        // S4: hidden2 ready

        // ---- head gemm + staged activation scatter ----
        {
            float c3[2][4];
            wgemm_ldsm<KS23, 2>(As2, S2_32, LO2, Bp3, NT3, nt03, 2, wrow3, lane, c3);
            #pragma unroll
            for (int j = 0; j < 2; j++)
                #pragma unroll
                for (int i = 0; i < 4; i++) {
                    int row = wrow3 + g + ((i >= 2) ? 8 : 0);
                    int col = 8 * (nt03 + j) + 2 * t + (i & 1);
                    float v = c3[j][i];
                    if (col < ACT) {
                        sMean[row * ACT + col] = tanhf(v);
                    } else if (col < NHEAD) {
                        float sp = fmaxf(v, 0.f) + log1pf(expf(-fabsf(v)));
                        sChol[row * 36 + c_pos[col - ACT]] = sp;
                    }
                }
            if (ptid < TILE_M) {
                #pragma unroll
                for (int j = 0; j < 15; j++) sChol[ptid * 36 + c_upper[j]] = 0.0f;
            }
        }
        PIPE_BAR();                                        // S5: staged

        // ---- coalesced writeback ----
        if ((tile + 1) * TILE_M <= B) {
            float4* pm = reinterpret_cast<float4*>(out + (size_t)tile * (TILE_M * ACT));
            const float4* sm4 = reinterpret_cast<const float4*>(sMean);
            for (int i = ptid; i < TILE_M * ACT / 4; i += 128) pm[i] = sm4[i];
            float4* pc = reinterpret_cast<float4*>(out + (size_t)B * ACT + (size_t)tile * (TILE_M * 36));
            const float4* sc4 = reinterpret_cast<const float4*>(sChol);
            for (int i = ptid; i < TILE_M * 36 / 4; i += 128) pc[i] = sc4[i];
        } else {
            int nrow = B - tile * TILE_M;
            for (int i = ptid; i < nrow * ACT; i += 128)
                out[(size_t)tile * (TILE_M * ACT) + i] = sMean[i];
            for (int i = ptid; i < nrow * 36; i += 128)
                out[(size_t)B * ACT + (size_t)tile * (TILE_M * 36) + i] = sChol[i];
        }
        PIPE_BAR();                                        // S6: stage free
    }
}

extern "C" void kernel_launch(void* const* d_in, const int* in_sizes, int n_in,
                              void* d_out, int out_size)
{
    const float* states = (const float*)d_in[0];
    const float* W1 = (const float*)d_in[1];
    const float* b1 = (const float*)d_in[2];
    const float* W2 = (const float*)d_in[3];
    const float* b2 = (const float*)d_in[4];
    const float* Wm = (const float*)d_in[5];
    const float* bm = (const float*)d_in[6];
    const float* Wc = (const float*)d_in[7];
    const float* bc = (const float*)d_in[8];
    float* out = (float*)d_out;

    const int B = in_sizes[0] / STATE;
    const int ntiles = (B + TILE_M - 1) / TILE_M;
    const size_t smem_bytes = (size_t)F_TOTAL * 4;   // 173568 B

    cudaFuncSetAttribute(actor_mma,
                         cudaFuncAttributeMaxDynamicSharedMemorySize,
                         (int)smem_bytes);

    int nstreams = (ntiles + 3) / 4;
    int grid = nstreams < 152 ? nstreams : 152;      // 1 CTA/SM, 4 pipelines each
    actor_mma<<<grid, TPB, smem_bytes>>>(states, W1, b1, W2, b2,
                                         Wm, bm, Wc, bc, out, B);
}

// round 13
// speedup vs baseline: 1.0967x; 1.0199x over previous
#include <cuda_runtime.h>
#include <cuda_fp16.h>
#include <cstdint>

#define TPB     512
#define TILE_M  32
#define STATE   24
#define L1D     100
#define L2D     100
#define NHEAD   27
#define ACT     6

#define NT12    13
#define NT3     4
#define KS1     2
#define KS23    7

#define S1_32   36
#define LO1     16
#define S2_32   116
#define LO2     56

// ---- smem layout (b32 word offsets) ----
#define F_BP1   0
#define F_BP2   (F_BP1 + KS1*NT12*32*4)         //  3328
#define F_BP3   (F_BP2 + KS23*NT12*32*4)        // 14976
#define F_PIPE  (F_BP3 + KS23*NT3*32*4)         // 18560
#define P_AS1   0
#define P_AS2   (TILE_M*S1_32)                  // 1152
#define P_ST    (P_AS2 + TILE_M*S2_32)          // 4864  (double-buffered staging)
#define ST_W    (TILE_M*36 + TILE_M*ACT)        // 1344 words per buffer
#define PIPE_W  (P_ST + 2*ST_W)                 // 7552 words
#define F_TOTAL (F_PIPE + 4*PIPE_W)             // 48768 words = 195072 B

__constant__ int c_pos[21]   = {0,6,7,12,13,14,18,19,20,21,24,25,26,27,28,30,31,32,33,34,35};
__constant__ int c_upper[15] = {1,2,3,4,5,8,9,10,11,15,16,17,22,23,29};

__device__ __forceinline__ uint32_t packh(__half a, __half b) {
    return (uint32_t)__half_as_ushort(a) | ((uint32_t)__half_as_ushort(b) << 16);
}
__device__ __forceinline__ void split2(float v0, float v1, uint32_t& hi, uint32_t& lo) {
    __half h0 = __float2half_rn(v0), h1 = __float2half_rn(v1);
    __half l0 = __float2half_rn(v0 - __half2float(h0));
    __half l1 = __float2half_rn(v1 - __half2float(h1));
    hi = packh(h0, h1); lo = packh(l0, l1);
}

__device__ __forceinline__ void mma16(float* c, const uint32_t* a, uint32_t b0, uint32_t b1) {
    asm volatile("mma.sync.aligned.m16n8k16.row.col.f32.f16.f16.f32 "
                 "{%0,%1,%2,%3},{%4,%5,%6,%7},{%8,%9},{%0,%1,%2,%3};"
                 : "+f"(c[0]), "+f"(c[1]), "+f"(c[2]), "+f"(c[3])
                 : "r"(a[0]), "r"(a[1]), "r"(a[2]), "r"(a[3]), "r"(b0), "r"(b1));
}

__device__ __forceinline__ void ldsm_x4(uint32_t (&r)[4], uint32_t saddr) {
    asm volatile("ldmatrix.sync.aligned.m8n8.x4.shared.b16 {%0,%1,%2,%3}, [%4];"
                 : "=r"(r[0]), "=r"(r[1]), "=r"(r[2]), "=r"(r[3]) : "r"(saddr));
}

#define PIPE_BAR() asm volatile("bar.sync %0, 128;" :: "r"(1 + pipe) : "memory")

extern __shared__ uint32_t smem[];

// 3-term f16 warp GEMM; 16 rows per warp (MT=1), A fragments via ldmatrix.x4.
template<int KS, int NTW>
__device__ __forceinline__ void wgemm_ldsm(const uint32_t* __restrict__ A32, int S32v, int LO,
                                           const uint4* __restrict__ Bp,
                                           int NTT, int nt0, int cnt,
                                           int wrow, int lane,
                                           float (&c)[NTW][4])
{
    #pragma unroll
    for (int j = 0; j < NTW; j++)
        #pragma unroll
        for (int i = 0; i < 4; i++) c[j][i] = 0.0f;

    const uint32_t abase = (uint32_t)__cvta_generic_to_shared(A32)
                         + ((uint32_t)((wrow + (lane & 15)) * S32v + (lane >> 4) * 4)) * 4u;

    #pragma unroll 1
    for (int ks = 0; ks < KS; ks++) {
        uint4 bfr[NTW];
        #pragma unroll
        for (int j = 0; j < NTW; j++)
            if (j < cnt) bfr[j] = Bp[(ks * NTT + nt0 + j) * 32 + lane];

        uint32_t ah[4], al[4];
        {
            const uint32_t ad = abase + (uint32_t)(ks * 32);
            ldsm_x4(ah, ad);
            ldsm_x4(al, ad + (uint32_t)(LO * 4));
        }

        #pragma unroll
        for (int term = 0; term < 3; term++)
            #pragma unroll
            for (int j = 0; j < NTW; j++) {
                if (j >= cnt) continue;
                uint32_t b0 = (term == 2) ? bfr[j].z : bfr[j].x;
                uint32_t b1 = (term == 2) ? bfr[j].w : bfr[j].y;
                mma16(c[j], (term == 1) ? al : ah, b0, b1);
            }
    }
}

template<int NTW>
__device__ __forceinline__ void epi_relu16(float (&c)[NTW][4], uint32_t* A2,
                                           int wrow, int nt0, int cnt, int g, int t)
{
    const int row = wrow + g;
    #pragma unroll
    for (int j = 0; j < NTW; j++) {
        if (j >= cnt) continue;
        const int nt = nt0 + j;
        if (nt == 12 && t >= 2) continue;      // cols >= 100
        const int pi = 4 * nt + t;
        uint32_t h, l;
        split2(fmaxf(c[j][0], 0.f), fmaxf(c[j][1], 0.f), h, l);
        A2[row * S2_32 + pi] = h;  A2[row * S2_32 + LO2 + pi] = l;
        split2(fmaxf(c[j][2], 0.f), fmaxf(c[j][3], 0.f), h, l);
        A2[(row + 8) * S2_32 + pi] = h;  A2[(row + 8) * S2_32 + LO2 + pi] = l;
    }
}

__global__ void __launch_bounds__(TPB, 1)
actor_mma(const float* __restrict__ states,
          const float* __restrict__ W1, const float* __restrict__ b1,
          const float* __restrict__ W2, const float* __restrict__ b2,
          const float* __restrict__ Wm, const float* __restrict__ bm,
          const float* __restrict__ Wc, const float* __restrict__ bc,
          float* __restrict__ out, int B)
{
    const int tid  = threadIdx.x;
    const int lane = tid & 31;
    const int wid  = tid >> 5;
    const int g    = lane >> 2;
    const int t    = lane & 3;

    const int pipe = wid >> 2;        // 0..3 — one warp per SMSP per pipeline
    const int w    = wid & 3;
    const int ptid = tid & 127;

    // layers 1,2 (M=32): M2 x N2 (balanced 7/6)
    const int wrow = (w & 1) * 16;
    const int nt0  = (w >> 1) * 7;
    const int ncnt = (w >> 1) ? 6 : 7;
    // head (M=32, N=32): M2 x N2
    const int wrow3 = (w & 1) * 16;
    const int nt03  = (w >> 1) * 2;

    uint32_t* pb   = smem + F_PIPE + pipe * PIPE_W;
    uint32_t* As1  = pb + P_AS1;
    uint32_t* As2  = pb + P_AS2;
    const uint4* Bp1 = reinterpret_cast<const uint4*>(smem + F_BP1);
    const uint4* Bp2 = reinterpret_cast<const uint4*>(smem + F_BP2);
    const uint4* Bp3 = reinterpret_cast<const uint4*>(smem + F_BP3);

    // ---- stage packed f16 hi/lo weight fragments (biases folded as K-column) ----
    for (int i = tid; i < KS1 * NT12 * 32; i += TPB) {
        int ln = i & 31, slot = i >> 5, ks = slot / NT12, nt = slot - ks * NT12;
        int n = (ln >> 2) + 8 * nt, k0 = 16 * ks + 2 * (ln & 3);
        float wv[4];
        #pragma unroll
        for (int q = 0; q < 4; q++) {
            int k = k0 + (q >> 1) * 8 + (q & 1);
            wv[q] = (n < L1D) ? (k < STATE ? W1[n * STATE + k] : (k == STATE ? b1[n] : 0.f)) : 0.f;
        }
        uint4 fr; uint32_t lo0, lo1;
        split2(wv[0], wv[1], fr.x, lo0); split2(wv[2], wv[3], fr.y, lo1);
        fr.z = lo0; fr.w = lo1;
        reinterpret_cast<uint4*>(smem + F_BP1)[i] = fr;
    }
    for (int i = tid; i < KS23 * NT12 * 32; i += TPB) {
        int ln = i & 31, slot = i >> 5, ks = slot / NT12, nt = slot - ks * NT12;
        int n = (ln >> 2) + 8 * nt, k0 = 16 * ks + 2 * (ln & 3);
        float wv[4];
        #pragma unroll
        for (int q = 0; q < 4; q++) {
            int k = k0 + (q >> 1) * 8 + (q & 1);
            wv[q] = (n < L2D) ? (k < L1D ? W2[n * L1D + k] : (k == L1D ? b2[n] : 0.f)) : 0.f;
        }
        uint4 fr; uint32_t lo0, lo1;
        split2(wv[0], wv[1], fr.x, lo0); split2(wv[2], wv[3], fr.y, lo1);
        fr.z = lo0; fr.w = lo1;
        reinterpret_cast<uint4*>(smem + F_BP2)[i] = fr;
    }
    for (int i = tid; i < KS23 * NT3 * 32; i += TPB) {
        int ln = i & 31, slot = i >> 5, ks = slot / NT3, nt = slot - ks * NT3;
        int n = (ln >> 2) + 8 * nt, k0 = 16 * ks + 2 * (ln & 3);
        float wv[4];
        #pragma unroll
        for (int q = 0; q < 4; q++) {
            int k = k0 + (q >> 1) * 8 + (q & 1);
            float v = 0.f;
            if (n < ACT)        v = k < L2D ? Wm[n * L2D + k] : (k == L2D ? bm[n] : 0.f);
            else if (n < NHEAD) v = k < L2D ? Wc[(n - ACT) * L2D + k] : (k == L2D ? bc[n - ACT] : 0.f);
            wv[q] = v;
        }
        uint4 fr; uint32_t lo0, lo1;
        split2(wv[0], wv[1], fr.x, lo0); split2(wv[2], wv[3], fr.y, lo1);
        fr.z = lo0; fr.w = lo1;
        reinterpret_cast<uint4*>(smem + F_BP3)[i] = fr;
    }
    // one-time per-pipeline activation pad init
    for (int i = ptid; i < TILE_M * S2_32; i += 128) As2[i] = 0u;
    __syncthreads();
    if (ptid < TILE_M) {
        const uint32_t one = packh(__float2half_rn(1.f), __ushort_as_half(0));
        As2[ptid * S2_32 + 50] = one;                 // bias col 100
        uint32_t* rr = As1 + ptid * S1_32;
        rr[12] = one;  rr[LO1 + 12] = 0u;             // bias col 24
        #pragma unroll
        for (int p = 13; p < 16; p++) { rr[p] = 0u; rr[LO1 + p] = 0u; }
    }
    __syncthreads();

    const int ntiles = (B + TILE_M - 1) / TILE_M;
    const int stride = gridDim.x * 4;
    const int tile0  = blockIdx.x * 4 + pipe;

    // ---- pre-loop: load + write X(tile0), then prefetch X(tile0+stride) ----
    float4 px0, px1, px2;
    if (ptid < 2 * TILE_M && tile0 < ntiles) {
        long m = (long)tile0 * TILE_M + (ptid >> 1); if (m >= B) m = B - 1;
        const float4* src = reinterpret_cast<const float4*>(states + m * STATE) + (ptid & 1) * 3;
        px0 = src[0]; px1 = src[1]; px2 = src[2];
        const int row = ptid >> 1, half = ptid & 1;
        uint32_t* rh = As1 + row * S1_32 + half * 6;
        uint32_t h, l;
        split2(px0.x, px0.y, h, l); rh[0] = h; rh[LO1 + 0] = l;
        split2(px0.z, px0.w, h, l); rh[1] = h; rh[LO1 + 1] = l;
        split2(px1.x, px1.y, h, l); rh[2] = h; rh[LO1 + 2] = l;
        split2(px1.z, px1.w, h, l); rh[3] = h; rh[LO1 + 3] = l;
        split2(px2.x, px2.y, h, l); rh[4] = h; rh[LO1 + 4] = l;
        split2(px2.z, px2.w, h, l); rh[5] = h; rh[LO1 + 5] = l;
    }
    PIPE_BAR();
    if (ptid < 2 * TILE_M && tile0 + stride < ntiles) {
        long m = (long)(tile0 + stride) * TILE_M + (ptid >> 1); if (m >= B) m = B - 1;
        const float4* src = reinterpret_cast<const float4*>(states + m * STATE) + (ptid & 1) * 3;
        px0 = src[0]; px1 = src[1]; px2 = src[2];
    }

    int buf = 0;
    for (int tile = tile0; tile < ntiles; tile += stride) {
        float* sChol = reinterpret_cast<float*>(pb + P_ST + buf * ST_W);
        float* sMean = sChol + TILE_M * 36;

        // ---- layer 1: As1 -> As2 ----
        {
            float c1[7][4];
            wgemm_ldsm<KS1, 7>(As1, S1_32, LO1, Bp1, NT12, nt0, ncnt, wrow, lane, c1);
            epi_relu16<7>(c1, As2, wrow, nt0, ncnt, g, t);
        }
        PIPE_BAR();                                        // S2: hidden1 ready + As1 reads done

        // ---- write next tile's X into As1 (overlaps layer-2 phase), prefetch next-next ----
        {
            int nxt = tile + stride;
            if (ptid < 2 * TILE_M && nxt < ntiles) {
                const int row = ptid >> 1, half = ptid & 1;
                uint32_t* rh = As1 + row * S1_32 + half * 6;
                uint32_t h, l;
                split2(px0.x, px0.y, h, l); rh[0] = h; rh[LO1 + 0] = l;
                split2(px0.z, px0.w, h, l); rh[1] = h; rh[LO1 + 1] = l;
                split2(px1.x, px1.y, h, l); rh[2] = h; rh[LO1 + 2] = l;
                split2(px1.z, px1.w, h, l); rh[3] = h; rh[LO1 + 3] = l;
                split2(px2.x, px2.y, h, l); rh[4] = h; rh[LO1 + 4] = l;
                split2(px2.z, px2.w, h, l); rh[5] = h; rh[LO1 + 5] = l;
            }
            int nxt2 = tile + 2 * stride;
            if (ptid < 2 * TILE_M && nxt2 < ntiles) {
                long m = (long)nxt2 * TILE_M + (ptid >> 1); if (m >= B) m = B - 1;
                const float4* src = reinterpret_cast<const float4*>(states + m * STATE) + (ptid & 1) * 3;
                px0 = src[0]; px1 = src[1]; px2 = src[2];
            }
        }

        // ---- layer 2: As2 -> As2 ----
        {
            float c2[7][4];
            wgemm_ldsm<KS23, 7>(As2, S2_32, LO2, Bp2, NT12, nt0, ncnt, wrow, lane, c2);
            PIPE_BAR();                                    // S3: As2 reads done
            epi_relu16<7>(c2, As2, wrow, nt0, ncnt, g, t);
        }
        PIPE_BAR();                                        // S4: hidden2 ready

        // ---- head gemm + staged activation scatter (buffer `buf`) ----
        {
            float c3[2][4];
            wgemm_ldsm<KS23, 2>(As2, S2_32, LO2, Bp3, NT3, nt03, 2, wrow3, lane, c3);
            #pragma unroll
            for (int j = 0; j < 2; j++)
                #pragma unroll
                for (int i = 0; i < 4; i++) {
                    int row = wrow3 + g + ((i >= 2) ? 8 : 0);
                    int col = 8 * (nt03 + j) + 2 * t + (i & 1);
                    float v = c3[j][i];
                    if (col < ACT) {
                        sMean[row * ACT + col] = tanhf(v);
                    } else if (col < NHEAD) {
                        float sp = fmaxf(v, 0.f) + log1pf(expf(-fabsf(v)));
                        sChol[row * 36 + c_pos[col - ACT]] = sp;
                    }
                }
            if (ptid < TILE_M) {
                #pragma unroll
                for (int j = 0; j < 15; j++) sChol[ptid * 36 + c_upper[j]] = 0.0f;
            }
        }
        PIPE_BAR();                                        // S5: staged

        // ---- coalesced writeback (no trailing barrier: next scatter uses buf^1) ----
        if ((tile + 1) * TILE_M <= B) {
            float4* pm = reinterpret_cast<float4*>(out + (size_t)tile * (TILE_M * ACT));
            const float4* sm4 = reinterpret_cast<const float4*>(sMean);
            for (int i = ptid; i < TILE_M * ACT / 4; i += 128) pm[i] = sm4[i];
            float4* pc = reinterpret_cast<float4*>(out + (size_t)B * ACT + (size_t)tile * (TILE_M * 36));
            const float4* sc4 = reinterpret_cast<const float4*>(sChol);
            for (int i = ptid; i < TILE_M * 36 / 4; i += 128) pc[i] = sc4[i];
        } else {
            int nrow = B - tile * TILE_M;
            for (int i = ptid; i < nrow * ACT; i += 128)
                out[(size_t)tile * (TILE_M * ACT) + i] = sMean[i];
            for (int i = ptid; i < nrow * 36; i += 128)
                out[(size_t)B * ACT + (size_t)tile * (TILE_M * 36) + i] = sChol[i];
        }
        buf ^= 1;
    }
}

extern "C" void kernel_launch(void* const* d_in, const int* in_sizes, int n_in,
                              void* d_out, int out_size)
{
    const float* states = (const float*)d_in[0];
    const float* W1 = (const float*)d_in[1];
    const float* b1 = (const float*)d_in[2];
    const float* W2 = (const float*)d_in[3];
    const float* b2 = (const float*)d_in[4];
    const float* Wm = (const float*)d_in[5];
    const float* bm = (const float*)d_in[6];
    const float* Wc = (const float*)d_in[7];
    const float* bc = (const float*)d_in[8];
    float* out = (float*)d_out;

    const int B = in_sizes[0] / STATE;
    const int ntiles = (B + TILE_M - 1) / TILE_M;
    const size_t smem_bytes = (size_t)F_TOTAL * 4;   // 195072 B

    cudaFuncSetAttribute(actor_mma,
                         cudaFuncAttributeMaxDynamicSharedMemorySize,
                         (int)smem_bytes);

    int nstreams = (ntiles + 3) / 4;
    int grid = nstreams < 152 ? nstreams : 152;      // 1 CTA/SM, 4 pipelines each
    actor_mma<<<grid, TPB, smem_bytes>>>(states, W1, b1, W2, b2,
                                         Wm, bm, Wc, bc, out, B);
}